// round 9
// baseline (speedup 1.0000x reference)
#include <cuda_runtime.h>

#define LSEQ   2048
#define DMODEL 512
#define NHEAD  8
#define DH     64
#define BATCH  2
#define BH     16
#define MROWS  4096
#define SHIFT  48.0f

typedef unsigned long long ull;

__device__ __forceinline__ ull pack2(float lo, float hi) {
    ull r; asm("mov.b64 %0, {%1, %2};" : "=l"(r) : "f"(lo), "f"(hi)); return r;
}
__device__ __forceinline__ ull dup2(float x) {
    ull r; asm("mov.b64 %0, {%1, %1};" : "=l"(r) : "f"(x)); return r;
}
__device__ __forceinline__ void unpack2(ull v, float& lo, float& hi) {
    asm("mov.b64 {%0, %1}, %2;" : "=f"(lo), "=f"(hi) : "l"(v));
}
__device__ __forceinline__ ull fma2(ull a, ull b, ull c) {
    ull d; asm("fma.rn.f32x2 %0, %1, %2, %3;" : "=l"(d) : "l"(a), "l"(b), "l"(c)); return d;
}
__device__ __forceinline__ ull mul2(ull a, ull b) {
    ull d; asm("mul.rn.f32x2 %0, %1, %2;" : "=l"(d) : "l"(a), "l"(b)); return d;
}

// ---------------- scratch ----------------
__device__ float g_qh[BH * LSEQ * DH];
__device__ float g_kh[BH * LSEQ * DH];
__device__ float g_vh[BH * LSEQ * DH];
__device__ float g_att[MROWS * DMODEL];
__device__ float g_rowsum[BH * LSEQ];
__device__ float g_srel[(size_t)BH * LSEQ * LSEQ];   // skewed rel logits (268MB)

// ---------------------------------------------------------------------------
// 64x64-tiled GEMM (f32x2): projections
// ---------------------------------------------------------------------------
__global__ __launch_bounds__(256) void gemm512(const float* __restrict__ A0,
                                               const float* __restrict__ W0,
                                               const float* __restrict__ b0,
                                               float* __restrict__ o0,
                                               const float* __restrict__ A1,
                                               const float* __restrict__ W1,
                                               const float* __restrict__ b1,
                                               float* __restrict__ o1,
                                               const float* __restrict__ A2,
                                               const float* __restrict__ W2,
                                               const float* __restrict__ b2,
                                               float* __restrict__ o2,
                                               int head_layout)
{
    const float* A = A0; const float* W = W0; const float* bias = b0; float* out = o0;
    if (blockIdx.z == 1) { A = A1; W = W1; bias = b1; out = o1; }
    if (blockIdx.z == 2) { A = A2; W = W2; bias = b2; out = o2; }

    __shared__ float As[64 * 16];
    __shared__ float Ws[16 * 64];
    const int tid = threadIdx.x;
    const int tx = tid & 15, ty = tid >> 4;
    const int m0 = blockIdx.x * 64;
    const int n0 = blockIdx.y * 64;

    ull acc2[4][2] = {};

    for (int k0 = 0; k0 < DMODEL; k0 += 16) {
        {
            int idx = tid * 4;
            int r = idx >> 4, c = idx & 15;
            *(float4*)(As + idx) = *(const float4*)(A + (size_t)(m0 + r) * DMODEL + k0 + c);
            int kk = idx >> 6, cc = idx & 63;
            *(float4*)(Ws + idx) = *(const float4*)(W + (size_t)(k0 + kk) * DMODEL + n0 + cc);
        }
        __syncthreads();
#pragma unroll
        for (int kk = 0; kk < 16; kk++) {
            ulonglong2 bp = *(const ulonglong2*)(Ws + kk * 64 + tx * 4);
#pragma unroll
            for (int u = 0; u < 4; u++) {
                ull ad = dup2(As[(ty * 4 + u) * 16 + kk]);
                acc2[u][0] = fma2(ad, bp.x, acc2[u][0]);
                acc2[u][1] = fma2(ad, bp.y, acc2[u][1]);
            }
        }
        __syncthreads();
    }

    float4 bb = *(const float4*)(bias + n0 + tx * 4);
#pragma unroll
    for (int u = 0; u < 4; u++) {
        int m = m0 + ty * 4 + u;
        float4 o;
        unpack2(acc2[u][0], o.x, o.y);
        unpack2(acc2[u][1], o.z, o.w);
        o.x += bb.x; o.y += bb.y; o.z += bb.z; o.w += bb.w;
        if (head_layout) {
            int b = m >> 11, l = m & (LSEQ - 1), h = n0 >> 6;
            *(float4*)(out + (((size_t)(b * NHEAD + h) * LSEQ + l) * DH + tx * 4)) = o;
        } else {
            *(float4*)(out + (size_t)m * DMODEL + n0 + tx * 4) = o;
        }
    }
}

// ---------------------------------------------------------------------------
// relsgemm: srel[bh][i][i-delta] = sum_d qh[bh][i][d] * key_rel[2047-delta][d]
// 64x64 tiles over (i, delta), lower triangle only (it >= dt).
// ---------------------------------------------------------------------------
__global__ __launch_bounds__(256) void relsgemm(const float* __restrict__ qh,
                                                const float* __restrict__ key_rel,
                                                float* __restrict__ srel)
{
    const int it = blockIdx.x, dt = blockIdx.y, bh = blockIdx.z;
    if (dt > it) return;
    const int i0 = it * 64, d0 = dt * 64;

    __shared__ float As[64 * 68];
    __shared__ float Bs[64 * 68];
    const int tid = threadIdx.x;
    const int tx = tid & 15, ty = tid >> 4;

    // fills: As[ii][kk] = qh row, Bs[dd][kk] = key_rel[2047-d0-dd][kk]
#pragma unroll
    for (int t = 0; t < 4; t++) {
        int idx = tid + t * 256;            // 1024 float4 slots
        int r = idx >> 4, c4 = idx & 15;
        *(float4*)(As + r * 68 + c4 * 4) =
            *(const float4*)(qh + ((size_t)bh * LSEQ + i0 + r) * DH + c4 * 4);
        *(float4*)(Bs + r * 68 + c4 * 4) =
            *(const float4*)(key_rel + (size_t)(2047 - d0 - r) * DH + c4 * 4);
    }
    __syncthreads();

    ull C2[4][4] = {};
#pragma unroll 4
    for (int kk = 0; kk < 64; kk += 2) {
        ull a2[4], b2[4];
#pragma unroll
        for (int u = 0; u < 4; u++) a2[u] = *(const ull*)(As + (4 * ty + u) * 68 + kk);
#pragma unroll
        for (int v = 0; v < 4; v++) b2[v] = *(const ull*)(Bs + (4 * tx + v) * 68 + kk);
#pragma unroll
        for (int u = 0; u < 4; u++)
#pragma unroll
            for (int v = 0; v < 4; v++) C2[u][v] = fma2(a2[u], b2[v], C2[u][v]);
    }

#pragma unroll
    for (int u = 0; u < 4; u++) {
        const int i = i0 + 4 * ty + u;
        float* row = srel + ((size_t)bh * LSEQ + i) * LSEQ;
#pragma unroll
        for (int v = 0; v < 4; v++) {
            float lo, hi; unpack2(C2[u][v], lo, hi);
            int j = i - (d0 + 4 * tx + v);
            if (j >= 0) row[j] = lo + hi;
        }
    }
}

// ---------------------------------------------------------------------------
// Fused causal attention: Sp init from srel, SIMT f32x2 QK, exp, plain PV.
// 256 threads, 8x8 frags, 128x128 tiles.
// ---------------------------------------------------------------------------
#define QT_OFF 0
#define KB_OFF 8448
#define PS_OFF 17152
#define SMEM_FLOATS 34048
#define SMEM_BYTES (SMEM_FLOATS * 4)

__global__ __launch_bounds__(256, 1) void attn_kernel(const float* __restrict__ qh,
                                                      const float* __restrict__ kh,
                                                      const float* __restrict__ vh,
                                                      const float* __restrict__ srel,
                                                      float* __restrict__ aw,
                                                      float* __restrict__ att,
                                                      float* __restrict__ rowsum)
{
    extern __shared__ float sm[];
    float* QT = sm + QT_OFF;
    float* KT = sm + KB_OFF;   // aliases VS
    float* VS = sm + KB_OFF;
    float* Ps = sm + PS_OFF;

    const int tid = threadIdx.x;
    const int tx = tid & 15, ty = tid >> 4;
    const int ib = 15 - blockIdx.x;       // heavy blocks first
    const int i0 = ib * 128;
    const int bh = blockIdx.y;
    const int ntiles = ib + 1;

    // QT[d][i] transpose fill
    const float* qbase = qh + ((size_t)bh * LSEQ + i0) * DH;
#pragma unroll
    for (int k = 0; k < 8; k++) {
        int idx = tid + k * 256;
        int i = idx & 127, d4 = idx >> 7;
        float4 t = *(const float4*)(qbase + i * 64 + d4 * 4);
        QT[(4 * d4 + 0) * 132 + i] = t.x;
        QT[(4 * d4 + 1) * 132 + i] = t.y;
        QT[(4 * d4 + 2) * 132 + i] = t.z;
        QT[(4 * d4 + 3) * 132 + i] = t.w;
    }

    float rs[8];
    ull Co[8][2];
#pragma unroll
    for (int u = 0; u < 8; u++) { rs[u] = 0.f; Co[u][0] = 0; Co[u][1] = 0; }

    for (int t = 0; t < ntiles; t++) {
        const int j0 = t * 128;

        __syncthreads();   // prior PV reads done / QT fill on first iter

        // KT[d][j] fill
        const float* kbase = kh + ((size_t)bh * LSEQ + j0) * DH;
#pragma unroll
        for (int k = 0; k < 8; k++) {
            int idx = tid + k * 256;
            int j = idx & 127, d4 = idx >> 7;
            float4 tt = *(const float4*)(kbase + j * 64 + d4 * 4);
            KT[(4 * d4 + 0) * 132 + j] = tt.x;
            KT[(4 * d4 + 1) * 132 + j] = tt.y;
            KT[(4 * d4 + 2) * 132 + j] = tt.z;
            KT[(4 * d4 + 3) * 132 + j] = tt.w;
        }
        __syncthreads();

        // ---- Sp init from srel (packed rows 2uu, 2uu+1) ----
        ull Sp[4][8];
#pragma unroll
        for (int uu = 0; uu < 4; uu++) {
            const int iA = i0 + 8 * ty + 2 * uu;
            const float* rA = srel + ((size_t)bh * LSEQ + iA) * LSEQ + j0 + 8 * tx;
            const float* rB = rA + LSEQ;
            float4 a0 = *(const float4*)(rA), a1 = *(const float4*)(rA + 4);
            float4 b0 = *(const float4*)(rB), b1 = *(const float4*)(rB + 4);
            Sp[uu][0] = pack2(a0.x, b0.x); Sp[uu][1] = pack2(a0.y, b0.y);
            Sp[uu][2] = pack2(a0.z, b0.z); Sp[uu][3] = pack2(a0.w, b0.w);
            Sp[uu][4] = pack2(a1.x, b1.x); Sp[uu][5] = pack2(a1.y, b1.y);
            Sp[uu][6] = pack2(a1.z, b1.z); Sp[uu][7] = pack2(a1.w, b1.w);
        }

        // ---- S += Q.K ----
        {
            const float* qp = QT + 8 * ty;
            const float* kp = KT + 8 * tx;
#pragma unroll 4
            for (int d = 0; d < 64; d++) {
                ulonglong2 aL = *(const ulonglong2*)qp;
                ulonglong2 aH = *(const ulonglong2*)(qp + 4);
                ull ap[4] = { aL.x, aL.y, aH.x, aH.y };
                float4 b0 = *(const float4*)kp;
                float4 b1 = *(const float4*)(kp + 4);
                ull bd[8] = { dup2(b0.x), dup2(b0.y), dup2(b0.z), dup2(b0.w),
                              dup2(b1.x), dup2(b1.y), dup2(b1.z), dup2(b1.w) };
#pragma unroll
                for (int uu = 0; uu < 4; uu++)
#pragma unroll
                    for (int v = 0; v < 8; v++)
                        Sp[uu][v] = fma2(ap[uu], bd[v], Sp[uu][v]);
                qp += 132; kp += 132;
            }
        }

        // ---- exp, mask, rowsum, Ps + aw stores ----
#pragma unroll
        for (int uu = 0; uu < 4; uu++) {
            const int iA = i0 + 8 * ty + 2 * uu;
            const int iB = iA + 1;
            float e0[8], e1[8];
#pragma unroll
            for (int v = 0; v < 8; v++) {
                float sA, sB;
                unpack2(Sp[uu][v], sA, sB);
                const int j = j0 + 8 * tx + v;
                e0[v] = (j <= iA) ? __expf(sA - SHIFT) : 0.f;
                e1[v] = (j <= iB) ? __expf(sB - SHIFT) : 0.f;
                rs[2 * uu]     += e0[v];
                rs[2 * uu + 1] += e1[v];
            }
            float* pr0 = Ps + (8 * ty + 2 * uu) * 132 + 8 * tx;
            float* pr1 = pr0 + 132;
            *(float4*)(pr0)     = make_float4(e0[0], e0[1], e0[2], e0[3]);
            *(float4*)(pr0 + 4) = make_float4(e0[4], e0[5], e0[6], e0[7]);
            *(float4*)(pr1)     = make_float4(e1[0], e1[1], e1[2], e1[3]);
            *(float4*)(pr1 + 4) = make_float4(e1[4], e1[5], e1[6], e1[7]);
            float4* dA = (float4*)(aw + ((size_t)bh * LSEQ + iA) * LSEQ + j0 + 8 * tx);
            float4* dB = (float4*)(aw + ((size_t)bh * LSEQ + iB) * LSEQ + j0 + 8 * tx);
            dA[0] = make_float4(e0[0], e0[1], e0[2], e0[3]);
            dA[1] = make_float4(e0[4], e0[5], e0[6], e0[7]);
            dB[0] = make_float4(e1[0], e1[1], e1[2], e1[3]);
            dB[1] = make_float4(e1[4], e1[5], e1[6], e1[7]);
        }
        __syncthreads();   // Ps written; KT reads done

        // ---- VS[j][d] fill ----
        const float* vbase = vh + ((size_t)bh * LSEQ + j0) * DH;
#pragma unroll
        for (int k = 0; k < 8; k++) {
            int idx = tid + k * 256;
            int j = idx >> 4, dd4 = idx & 15;
            *(float4*)(VS + j * 68 + dd4 * 4) = *(const float4*)(vbase + j * 64 + dd4 * 4);
        }
        __syncthreads();

        // ---- PV: Co += p * V (4-jj batched) ----
        for (int jb = 0; jb < 128; jb += 8) {
#pragma unroll
            for (int half = 0; half < 2; half++) {
                float4 p4[8];
#pragma unroll
                for (int u = 0; u < 8; u++)
                    p4[u] = *(const float4*)(Ps + (8 * ty + u) * 132 + jb + 4 * half);
                ull v0[4], v1[4];
#pragma unroll
                for (int q = 0; q < 4; q++) {
                    const int jj = jb + 4 * half + q;
                    v0[q] = *(const ull*)(VS + jj * 68 + 2 * tx);
                    v1[q] = *(const ull*)(VS + jj * 68 + 32 + 2 * tx);
                }
#pragma unroll
                for (int q = 0; q < 4; q++)
#pragma unroll
                    for (int u = 0; u < 8; u++) {
                        ull pd = dup2(((const float*)&p4[u])[q]);
                        Co[u][0] = fma2(pd, v0[q], Co[u][0]);
                        Co[u][1] = fma2(pd, v1[q], Co[u][1]);
                    }
            }
        }
    }

    // ---- finalize: reduce rowsums, scale PV, store ----
#pragma unroll
    for (int u = 0; u < 8; u++) {
#pragma unroll
        for (int o = 8; o > 0; o >>= 1)
            rs[u] += __shfl_xor_sync(0xffffffffu, rs[u], o);
    }

    const int b = bh >> 3, h = bh & 7;
#pragma unroll
    for (int u = 0; u < 8; u++) {
        const int i = i0 + 8 * ty + u;
        const float inv = 1.0f / rs[u];
        if (tx == 0) rowsum[bh * LSEQ + i] = rs[u];
        ull invd = dup2(inv);
        float* base = att + ((size_t)(b * LSEQ + i)) * DMODEL + h * DH;
        *(ull*)(base + 2 * tx)      = mul2(Co[u][0], invd);
        *(ull*)(base + 32 + 2 * tx) = mul2(Co[u][1], invd);
    }
}

// ---------------------------------------------------------------------------
// relpv: att[b*L+i][h*64+d] += (sum_delta e[i][i-delta] * val_rel[2047-delta][d]) / rs
// 64-row i-tiles; k-loop over delta tiles 0..it.
// ---------------------------------------------------------------------------
__global__ __launch_bounds__(256) void relpv(const float* __restrict__ aw,
                                             const float* __restrict__ val_rel,
                                             const float* __restrict__ rowsum,
                                             float* __restrict__ att)
{
    const int it = 31 - blockIdx.x;       // LPT
    const int bh = blockIdx.y;
    const int i0 = it * 64;

    __shared__ float As[64 * 68];
    __shared__ float Bs[64 * 68];
    const int tid = threadIdx.x;
    const int tx = tid & 15, ty = tid >> 4;

    ull C2[4][2] = {};

    for (int dt = 0; dt <= it; dt++) {
        const int d0 = dt * 64;
        __syncthreads();
        // As[ii][kk] = e[i][i - (d0+kk)]  (0 if j<0; only possible when dt==it)
#pragma unroll
        for (int t = 0; t < 16; t++) {
            int idx = tid + t * 256;       // 4096 scalar slots
            int ii = idx >> 6, kk = idx & 63;
            int i = i0 + ii;
            int j = i - d0 - kk;
            As[ii * 68 + kk] = (j >= 0) ?
                aw[((size_t)bh * LSEQ + i) * LSEQ + j] : 0.f;
        }
        // Bs[kk][d] = val_rel[2047 - (d0+kk)][d]
#pragma unroll
        for (int t = 0; t < 4; t++) {
            int idx = tid + t * 256;
            int r = idx >> 4, c4 = idx & 15;
            *(float4*)(Bs + r * 68 + c4 * 4) =
                *(const float4*)(val_rel + (size_t)(2047 - d0 - r) * DH + c4 * 4);
        }
        __syncthreads();

#pragma unroll 4
        for (int kk = 0; kk < 64; kk++) {
            ull b0 = *(const ull*)(Bs + kk * 68 + 4 * tx);
            ull b1 = *(const ull*)(Bs + kk * 68 + 4 * tx + 2);
#pragma unroll
            for (int u = 0; u < 4; u++) {
                ull a = dup2(As[(4 * ty + u) * 68 + kk]);
                C2[u][0] = fma2(a, b0, C2[u][0]);
                C2[u][1] = fma2(a, b1, C2[u][1]);
            }
        }
    }

    const int b = bh >> 3, h = bh & 7;
#pragma unroll
    for (int u = 0; u < 4; u++) {
        const int i = i0 + 4 * ty + u;
        const float inv = 1.0f / rowsum[bh * LSEQ + i];
        float* dst = att + ((size_t)(b * LSEQ + i)) * DMODEL + h * DH + 4 * tx;
        float l0, h0, l1, h1;
        unpack2(C2[u][0], l0, h0);
        unpack2(C2[u][1], l1, h1);
        float4 cur = *(float4*)dst;
        cur.x += l0 * inv; cur.y += h0 * inv;
        cur.z += l1 * inv; cur.w += h1 * inv;
        *(float4*)dst = cur;
    }
}

// ---------------------------------------------------------------------------
__global__ __launch_bounds__(256) void norm_aw(float* __restrict__ aw,
                                               const float* __restrict__ rowsum)
{
    const int row = blockIdx.x;
    const int i = row & (LSEQ - 1);
    const float inv = 1.0f / rowsum[row];
    float4* p = (float4*)(aw + (size_t)row * LSEQ);
#pragma unroll
    for (int k = 0; k < 2; k++) {
        int c4 = threadIdx.x + k * 256;
        int j = c4 * 4;
        float4 v;
        if (j + 3 <= i) {
            v = p[c4];
            v.x *= inv; v.y *= inv; v.z *= inv; v.w *= inv;
        } else if (j > i) {
            v = make_float4(0.f, 0.f, 0.f, 0.f);
        } else {
            v = p[c4];
            v.x = (j     <= i) ? v.x * inv : 0.f;
            v.y = (j + 1 <= i) ? v.y * inv : 0.f;
            v.z = (j + 2 <= i) ? v.z * inv : 0.f;
            v.w = (j + 3 <= i) ? v.w * inv : 0.f;
        }
        p[c4] = v;
    }
}

// ---------------------------------------------------------------------------
extern "C" void kernel_launch(void* const* d_in, const int* in_sizes, int n_in,
                              void* d_out, int out_size)
{
    const float* q       = (const float*)d_in[0];
    const float* k       = (const float*)d_in[1];
    const float* v       = (const float*)d_in[2];
    const float* wq      = (const float*)d_in[4];
    const float* bq      = (const float*)d_in[5];
    const float* wk      = (const float*)d_in[6];
    const float* bk      = (const float*)d_in[7];
    const float* wv      = (const float*)d_in[8];
    const float* bv      = (const float*)d_in[9];
    const float* wo      = (const float*)d_in[10];
    const float* bo      = (const float*)d_in[11];
    const float* key_rel = (const float*)d_in[12];
    const float* val_rel = (const float*)d_in[13];

    float* out = (float*)d_out;
    const long long OUT_ELEMS = (long long)BATCH * LSEQ * DMODEL;
    const long long AW_ELEMS  = (long long)BH * LSEQ * LSEQ;
    const int write_aw = ((long long)out_size >= OUT_ELEMS + AW_ELEMS) ? 1 : 0;

    float *qh, *kh, *vh, *att, *rsum, *srel;
    cudaGetSymbolAddress((void**)&qh,   g_qh);
    cudaGetSymbolAddress((void**)&kh,   g_kh);
    cudaGetSymbolAddress((void**)&vh,   g_vh);
    cudaGetSymbolAddress((void**)&att,  g_att);
    cudaGetSymbolAddress((void**)&rsum, g_rowsum);
    cudaGetSymbolAddress((void**)&srel, g_srel);

    float* aw = write_aw ? (out + OUT_ELEMS) : srel;   // fallback: reuse srel buffer

    cudaFuncSetAttribute(attn_kernel, cudaFuncAttributeMaxDynamicSharedMemorySize, SMEM_BYTES);

    dim3 gGrid3(MROWS / 64, DMODEL / 64, 3);
    gemm512<<<gGrid3, 256>>>(q, wq, bq, qh,  k, wk, bk, kh,  v, wv, bv, vh, 1);

    relsgemm<<<dim3(32, 32, BH), 256>>>(qh, key_rel, srel);

    attn_kernel<<<dim3(LSEQ / 128, BH), 256, SMEM_BYTES>>>(qh, kh, vh, srel,
                                                           aw, att, rsum);

    relpv<<<dim3(32, BH), 256>>>(aw, val_rel, rsum, att);

    if (write_aw)
        norm_aw<<<BH * LSEQ, 256>>>(aw, rsum);

    dim3 gGrid(MROWS / 64, DMODEL / 64, 1);
    gemm512<<<gGrid, 256>>>(att, wo, bo, out,  att, wo, bo, out,  att, wo, bo, out, 0);
}

// round 10
// speedup vs baseline: 1.1918x; 1.1918x over previous
#include <cuda_runtime.h>

#define LSEQ   2048
#define DMODEL 512
#define NHEAD  8
#define DH     64
#define BATCH  2
#define BH     16
#define MROWS  4096
#define SHIFT  48.0f

typedef unsigned long long ull;

__device__ __forceinline__ ull pack2(float lo, float hi) {
    ull r; asm("mov.b64 %0, {%1, %2};" : "=l"(r) : "f"(lo), "f"(hi)); return r;
}
__device__ __forceinline__ ull dup2(float x) {
    ull r; asm("mov.b64 %0, {%1, %1};" : "=l"(r) : "f"(x)); return r;
}
__device__ __forceinline__ void unpack2(ull v, float& lo, float& hi) {
    asm("mov.b64 {%0, %1}, %2;" : "=f"(lo), "=f"(hi) : "l"(v));
}
__device__ __forceinline__ ull fma2(ull a, ull b, ull c) {
    ull d; asm("fma.rn.f32x2 %0, %1, %2, %3;" : "=l"(d) : "l"(a), "l"(b), "l"(c)); return d;
}
__device__ __forceinline__ ull add2(ull a, ull b) {
    ull d; asm("add.rn.f32x2 %0, %1, %2;" : "=l"(d) : "l"(a), "l"(b)); return d;
}
__device__ __forceinline__ ull mul2(ull a, ull b) {
    ull d; asm("mul.rn.f32x2 %0, %1, %2;" : "=l"(d) : "l"(a), "l"(b)); return d;
}

// ---------------- scratch ----------------
__device__ float g_qh[BH * LSEQ * DH];
__device__ float g_kh[BH * LSEQ * DH];
__device__ float g_vh[BH * LSEQ * DH];
__device__ float g_att[MROWS * DMODEL];
__device__ float g_rowsum[BH * LSEQ];

// ---------------------------------------------------------------------------
// 64x64-tiled GEMM (f32x2): projections (unchanged, near fp32 roofline)
// ---------------------------------------------------------------------------
__global__ __launch_bounds__(256) void gemm512(const float* __restrict__ A0,
                                               const float* __restrict__ W0,
                                               const float* __restrict__ b0,
                                               float* __restrict__ o0,
                                               const float* __restrict__ A1,
                                               const float* __restrict__ W1,
                                               const float* __restrict__ b1,
                                               float* __restrict__ o1,
                                               const float* __restrict__ A2,
                                               const float* __restrict__ W2,
                                               const float* __restrict__ b2,
                                               float* __restrict__ o2,
                                               int head_layout)
{
    const float* A = A0; const float* W = W0; const float* bias = b0; float* out = o0;
    if (blockIdx.z == 1) { A = A1; W = W1; bias = b1; out = o1; }
    if (blockIdx.z == 2) { A = A2; W = W2; bias = b2; out = o2; }

    __shared__ float As[64 * 16];
    __shared__ float Ws[16 * 64];
    const int tid = threadIdx.x;
    const int tx = tid & 15, ty = tid >> 4;
    const int m0 = blockIdx.x * 64;
    const int n0 = blockIdx.y * 64;

    ull acc2[4][2] = {};

    for (int k0 = 0; k0 < DMODEL; k0 += 16) {
        {
            int idx = tid * 4;
            int r = idx >> 4, c = idx & 15;
            *(float4*)(As + idx) = *(const float4*)(A + (size_t)(m0 + r) * DMODEL + k0 + c);
            int kk = idx >> 6, cc = idx & 63;
            *(float4*)(Ws + idx) = *(const float4*)(W + (size_t)(k0 + kk) * DMODEL + n0 + cc);
        }
        __syncthreads();
#pragma unroll
        for (int kk = 0; kk < 16; kk++) {
            ulonglong2 bp = *(const ulonglong2*)(Ws + kk * 64 + tx * 4);
#pragma unroll
            for (int u = 0; u < 4; u++) {
                ull ad = dup2(As[(ty * 4 + u) * 16 + kk]);
                acc2[u][0] = fma2(ad, bp.x, acc2[u][0]);
                acc2[u][1] = fma2(ad, bp.y, acc2[u][1]);
            }
        }
        __syncthreads();
    }

    float4 bb = *(const float4*)(bias + n0 + tx * 4);
#pragma unroll
    for (int u = 0; u < 4; u++) {
        int m = m0 + ty * 4 + u;
        float4 o;
        unpack2(acc2[u][0], o.x, o.y);
        unpack2(acc2[u][1], o.z, o.w);
        o.x += bb.x; o.y += bb.y; o.z += bb.z; o.w += bb.w;
        if (head_layout) {
            int b = m >> 11, l = m & (LSEQ - 1), h = n0 >> 6;
            *(float4*)(out + (((size_t)(b * NHEAD + h) * LSEQ + l) * DH + tx * 4)) = o;
        } else {
            *(float4*)(out + (size_t)m * DMODEL + n0 + tx * 4) = o;
        }
    }
}

// ---------------------------------------------------------------------------
// Fused causal attention, f32x2, 64x64 tiles, 4x4 frags, 256 threads.
// 88KB smem -> 2 CTAs/SM (4 warps/SMSP) for latency hiding.
// Smem (floats): QT[64][68] | KT/VS[64][68] | WT[64][132]/WV[132][68] | Ps[64][68]
// ---------------------------------------------------------------------------
#define QT_OFF 0
#define KB_OFF 4352
#define WB_OFF 8704
#define PS_OFF 17680
#define SMEM_FLOATS 22032
#define SMEM_BYTES (SMEM_FLOATS * 4)

__global__ __launch_bounds__(256, 2) void attn_kernel(const float* __restrict__ qh,
                                                      const float* __restrict__ kh,
                                                      const float* __restrict__ vh,
                                                      const float* __restrict__ key_rel,
                                                      const float* __restrict__ val_rel,
                                                      float* __restrict__ aw,
                                                      float* __restrict__ att,
                                                      float* __restrict__ rowsum,
                                                      int write_aw)
{
    extern __shared__ float sm[];
    float* QT = sm + QT_OFF;   // [d][i], stride 68
    float* KT = sm + KB_OFF;   // [d][j], stride 68 (aliases VS [j][d])
    float* VS = sm + KB_OFF;
    float* WT = sm + WB_OFF;   // [d][si], stride 132 (aliases WV [s][d] stride 68)
    float* WV = sm + WB_OFF;
    float* Ps = sm + PS_OFF;   // [i][j], stride 68

    const int tid = threadIdx.x;
    const int tx = tid & 15, ty = tid >> 4;
    const int ib = 31 - blockIdx.x;       // heavy diagonal blocks first (LPT)
    const int i0 = ib * 64;
    const int bh = blockIdx.y;
    const int ntiles = ib + 1;

    // ---- QT fill (transpose): QT[d][i] ----
    const float* qbase = qh + ((size_t)bh * LSEQ + i0) * DH;
#pragma unroll
    for (int k = 0; k < 4; k++) {
        int idx = tid + k * 256;          // 1024 float4 groups
        int i = idx & 63, d4 = idx >> 6;
        float4 t = *(const float4*)(qbase + i * 64 + d4 * 4);
        QT[(4 * d4 + 0) * 68 + i] = t.x;
        QT[(4 * d4 + 1) * 68 + i] = t.y;
        QT[(4 * d4 + 2) * 68 + i] = t.z;
        QT[(4 * d4 + 3) * 68 + i] = t.w;
    }

    float rs[4];
    ull Cv[4][2], Cw[4][2];
#pragma unroll
    for (int u = 0; u < 4; u++) {
        rs[u] = 0.f;
        Cv[u][0] = 0; Cv[u][1] = 0;
        Cw[u][0] = 0; Cw[u][1] = 0;
    }

    for (int t = 0; t < ntiles; t++) {
        const int j0 = t * 64;
        const int D0 = i0 - j0 - 63;      // delta = s + D0 (WV), si-1+D0 (WT)

        __syncthreads();   // prior PV reads done / QT fill on first iter

        // ---- KT fill (transpose): KT[d][j] ----
        const float* kbase = kh + ((size_t)bh * LSEQ + j0) * DH;
#pragma unroll
        for (int k = 0; k < 4; k++) {
            int idx = tid + k * 256;
            int j = idx & 63, d4 = idx >> 6;
            float4 tt = *(const float4*)(kbase + j * 64 + d4 * 4);
            KT[(4 * d4 + 0) * 68 + j] = tt.x;
            KT[(4 * d4 + 1) * 68 + j] = tt.y;
            KT[(4 * d4 + 2) * 68 + j] = tt.z;
            KT[(4 * d4 + 3) * 68 + j] = tt.w;
        }
        // ---- WT fill: WT[d][si], si in [0,128), delta = si-1+D0 ----
#pragma unroll
        for (int k = 0; k < 8; k++) {
            int idx = tid + k * 256;      // 0..2047
            int si = idx & 127, d4 = idx >> 7;
            int delta = si - 1 + D0;
            float4 tt = make_float4(0.f, 0.f, 0.f, 0.f);
            if (delta >= 0 && delta < LSEQ)
                tt = *(const float4*)(key_rel + (size_t)(LSEQ - 1 - delta) * DH + d4 * 4);
            WT[(4 * d4 + 0) * 132 + si] = tt.x;
            WT[(4 * d4 + 1) * 132 + si] = tt.y;
            WT[(4 * d4 + 2) * 132 + si] = tt.z;
            WT[(4 * d4 + 3) * 132 + si] = tt.w;
        }
        __syncthreads();

        // ---- S: Sp[uu][v] packs rows (4ty+2uu, 4ty+2uu+1), col 4tx+v ----
        ull Sp[2][4] = {};
        {
            const float* qp = QT + 4 * ty;
            const float* kp = KT + 4 * tx;
            const float* wp = WT + (60 + 4 * ty - 4 * tx);
#pragma unroll 4
            for (int d = 0; d < 64; d++) {
                ulonglong2 aP = *(const ulonglong2*)qp;     // ap[0]=rows(0,1), ap[1]=rows(2,3)
                float4 b = *(const float4*)kp;
                ull bd[4] = { dup2(b.x), dup2(b.y), dup2(b.z), dup2(b.w) };
                float4 w0 = *(const float4*)wp;             // wv[0..3]
                float4 w1 = *(const float4*)(wp + 4);       // wv[4..7]
                float wv[8] = { w0.x, w0.y, w0.z, w0.w, w1.x, w1.y, w1.z, w1.w };
                ull P[7];
#pragma unroll
                for (int o = 1; o <= 6; o++) P[o] = pack2(wv[o], wv[o + 1]);
#pragma unroll
                for (int v = 0; v < 4; v++) {
                    Sp[0][v] = fma2(aP.x, bd[v], Sp[0][v]);
                    Sp[0][v] = fma2(aP.x, P[4 - v], Sp[0][v]);
                    Sp[1][v] = fma2(aP.y, bd[v], Sp[1][v]);
                    Sp[1][v] = fma2(aP.y, P[6 - v], Sp[1][v]);
                }
                qp += 68; kp += 68; wp += 132;
            }
        }

        // ---- exp, mask, rowsum, Ps + aw stores ----
#pragma unroll
        for (int uu = 0; uu < 2; uu++) {
            const int iA = i0 + 4 * ty + 2 * uu;
            const int iB = iA + 1;
            float e0[4], e1[4];
#pragma unroll
            for (int v = 0; v < 4; v++) {
                float sA, sB;
                unpack2(Sp[uu][v], sA, sB);
                const int j = j0 + 4 * tx + v;
                e0[v] = (j <= iA) ? __expf(sA - SHIFT) : 0.f;
                e1[v] = (j <= iB) ? __expf(sB - SHIFT) : 0.f;
                rs[2 * uu]     += e0[v];
                rs[2 * uu + 1] += e1[v];
            }
            float* pr0 = Ps + (4 * ty + 2 * uu) * 68 + 4 * tx;
            *(float4*)(pr0)      = make_float4(e0[0], e0[1], e0[2], e0[3]);
            *(float4*)(pr0 + 68) = make_float4(e1[0], e1[1], e1[2], e1[3]);
            if (write_aw) {
                *(float4*)(aw + ((size_t)bh * LSEQ + iA) * LSEQ + j0 + 4 * tx) =
                    make_float4(e0[0], e0[1], e0[2], e0[3]);
                *(float4*)(aw + ((size_t)bh * LSEQ + iB) * LSEQ + j0 + 4 * tx) =
                    make_float4(e1[0], e1[1], e1[2], e1[3]);
            }
        }
        __syncthreads();   // Ps written; KT/WT reads done

        // ---- PV fills: VS[j][d], WV[s][d] ----
        const float* vbase = vh + ((size_t)bh * LSEQ + j0) * DH;
#pragma unroll
        for (int k = 0; k < 4; k++) {
            int idx = tid + k * 256;
            int j = idx >> 4, d4 = idx & 15;
            *(float4*)(VS + j * 68 + d4 * 4) = *(const float4*)(vbase + j * 64 + d4 * 4);
        }
#pragma unroll
        for (int k = 0; k < 8; k++) {
            int idx = tid + k * 256;      // s 0..127
            int s = idx >> 4, d4 = idx & 15;
            int delta = s + D0;
            float4 tt = make_float4(0.f, 0.f, 0.f, 0.f);
            if (delta >= 0 && delta < LSEQ)
                tt = *(const float4*)(val_rel + (size_t)(LSEQ - 1 - delta) * DH + d4 * 4);
            *(float4*)(WV + s * 68 + d4 * 4) = tt;
        }
        __syncthreads();

        // ---- PV: Cv += p*V, Cw += p*Wwin (4-slot register sliding window) ----
        ulonglong2 wr[4];
#pragma unroll
        for (int u = 0; u < 4; u++)
            wr[u] = *(const ulonglong2*)(WV + (63 + 4 * ty + u) * 68 + 4 * tx);

        for (int jb = 0; jb < 64; jb += 4) {
            float4 p4[4];
#pragma unroll
            for (int u = 0; u < 4; u++)
                p4[u] = *(const float4*)(Ps + (4 * ty + u) * 68 + jb);
            ulonglong2 vv[4];
#pragma unroll
            for (int q = 0; q < 4; q++)
                vv[q] = *(const ulonglong2*)(VS + (jb + q) * 68 + 4 * tx);
#pragma unroll
            for (int q = 0; q < 4; q++) {
#pragma unroll
                for (int u = 0; u < 4; u++) {
                    ull pd = dup2(((const float*)&p4[u])[q]);
                    const int sl = (u - q) & 3;
                    Cv[u][0] = fma2(pd, vv[q].x, Cv[u][0]);
                    Cv[u][1] = fma2(pd, vv[q].y, Cv[u][1]);
                    Cw[u][0] = fma2(pd, wr[sl].x, Cw[u][0]);
                    Cw[u][1] = fma2(pd, wr[sl].y, Cw[u][1]);
                }
                const int rn = 62 + 4 * ty - jb - q;
                const int sln = (-(q + 1)) & 3;
                if (rn >= 0) {
                    wr[sln] = *(const ulonglong2*)(WV + rn * 68 + 4 * tx);
                } else {
                    wr[sln].x = 0; wr[sln].y = 0;
                }
            }
        }
    }

    // ---- finalize: reduce rowsums over 16 tx lanes, scale, store ----
#pragma unroll
    for (int u = 0; u < 4; u++) {
#pragma unroll
        for (int o = 8; o > 0; o >>= 1)
            rs[u] += __shfl_xor_sync(0xffffffffu, rs[u], o);
    }

    const int b = bh >> 3, h = bh & 7;
#pragma unroll
    for (int u = 0; u < 4; u++) {
        const int i = i0 + 4 * ty + u;
        const float inv = 1.0f / rs[u];
        if (tx == 0) rowsum[bh * LSEQ + i] = rs[u];
        ull invd = dup2(inv);
        float* dst = att + ((size_t)(b * LSEQ + i)) * DMODEL + h * DH + 4 * tx;
        ull r0 = mul2(add2(Cv[u][0], Cw[u][0]), invd);
        ull r1 = mul2(add2(Cv[u][1], Cw[u][1]), invd);
        *(ull*)(dst)     = r0;
        *(ull*)(dst + 2) = r1;
    }
}

// ---------------------------------------------------------------------------
__global__ __launch_bounds__(256) void norm_aw(float* __restrict__ aw,
                                               const float* __restrict__ rowsum)
{
    const int row = blockIdx.x;
    const int i = row & (LSEQ - 1);
    const float inv = 1.0f / rowsum[row];
    float4* p = (float4*)(aw + (size_t)row * LSEQ);
#pragma unroll
    for (int k = 0; k < 2; k++) {
        int c4 = threadIdx.x + k * 256;
        int j = c4 * 4;
        float4 v;
        if (j + 3 <= i) {
            v = p[c4];
            v.x *= inv; v.y *= inv; v.z *= inv; v.w *= inv;
        } else if (j > i) {
            v = make_float4(0.f, 0.f, 0.f, 0.f);
        } else {
            v = p[c4];
            v.x = (j     <= i) ? v.x * inv : 0.f;
            v.y = (j + 1 <= i) ? v.y * inv : 0.f;
            v.z = (j + 2 <= i) ? v.z * inv : 0.f;
            v.w = (j + 3 <= i) ? v.w * inv : 0.f;
        }
        p[c4] = v;
    }
}

// ---------------------------------------------------------------------------
extern "C" void kernel_launch(void* const* d_in, const int* in_sizes, int n_in,
                              void* d_out, int out_size)
{
    const float* q       = (const float*)d_in[0];
    const float* k       = (const float*)d_in[1];
    const float* v       = (const float*)d_in[2];
    const float* wq      = (const float*)d_in[4];
    const float* bq      = (const float*)d_in[5];
    const float* wk      = (const float*)d_in[6];
    const float* bk      = (const float*)d_in[7];
    const float* wv      = (const float*)d_in[8];
    const float* bv      = (const float*)d_in[9];
    const float* wo      = (const float*)d_in[10];
    const float* bo      = (const float*)d_in[11];
    const float* key_rel = (const float*)d_in[12];
    const float* val_rel = (const float*)d_in[13];

    float* out = (float*)d_out;
    const long long OUT_ELEMS = (long long)BATCH * LSEQ * DMODEL;
    const long long AW_ELEMS  = (long long)BH * LSEQ * LSEQ;
    const int write_aw = ((long long)out_size >= OUT_ELEMS + AW_ELEMS) ? 1 : 0;
    float* aw = out + OUT_ELEMS;

    float *qh, *kh, *vh, *att, *rsum;
    cudaGetSymbolAddress((void**)&qh,   g_qh);
    cudaGetSymbolAddress((void**)&kh,   g_kh);
    cudaGetSymbolAddress((void**)&vh,   g_vh);
    cudaGetSymbolAddress((void**)&att,  g_att);
    cudaGetSymbolAddress((void**)&rsum, g_rowsum);

    cudaFuncSetAttribute(attn_kernel, cudaFuncAttributeMaxDynamicSharedMemorySize, SMEM_BYTES);

    dim3 gGrid3(MROWS / 64, DMODEL / 64, 3);
    gemm512<<<gGrid3, 256>>>(q, wq, bq, qh,  k, wk, bk, kh,  v, wv, bv, vh, 1);

    attn_kernel<<<dim3(LSEQ / 64, BH), 256, SMEM_BYTES>>>(qh, kh, vh, key_rel, val_rel,
                                                          aw, att, rsum, write_aw);
    if (write_aw)
        norm_aw<<<BH * LSEQ, 256>>>(aw, rsum);

    dim3 gGrid(MROWS / 64, DMODEL / 64, 1);
    gemm512<<<gGrid, 256>>>(att, wo, bo, out,  att, wo, bo, out,  att, wo, bo, out, 0);
}